// round 13
// baseline (speedup 1.0000x reference)
#include <cuda_runtime.h>
#include <cstdint>

// out = self_tensor; out[sorted_index[i], :] += value[i, :]
// N=262144 rows, M=1048576 updates, D=128 cols, fp32. sorted_index SORTED,
// delivered as int32 by the harness.
//
// SINGLE-LAUNCH fused version of the converged two-pass champion:
//   blocks [0, P1): build CSR row-start offsets g_starts (grid-stride),
//     __threadfence, then arrive on g_p1_done counter.
//   blocks [P1, P1+P2): champion pass-2, unchanged: one warp per output
//     row; issue the (pass-1-independent) self-row load first, then one
//     thread spins until g_p1_done == P1, __syncthreads, read starts,
//     stream the value run (float4, 4-deep), write once.
// Deadlock-free: blocks issue in bid order; pass-1 blocks never wait and
//   P1=512 < wave-1 residency, so pass-1 always drains. Last pass-2 block
//   resets both counters -> deterministic across graph replays. Zero
//   atomics on data, minimal 776MB traffic.

static constexpr int D4 = 32;          // 128 floats = 32 float4/row
static constexpr int MAX_ROWS = 262144;
static constexpr int P1_BLOCKS = 512;
static constexpr int THREADS = 128;    // 4 warps/block

__device__ int g_starts[MAX_ROWS + 1];
__device__ int g_p1_done = 0;
__device__ int g_p2_done = 0;

__global__ void __launch_bounds__(THREADS)
fused_two_pass_kernel(const float* __restrict__ self_t,
                      const float* __restrict__ value,
                      const int* __restrict__ idx,
                      float* __restrict__ out,
                      int n_rows, int m, int p2_blocks) {
    const int bid = blockIdx.x;
    const int tid = threadIdx.x;

    if (bid < P1_BLOCKS) {
        // ---------- pass 1: build g_starts ----------
        const int stride = P1_BLOCKS * THREADS;
        for (int i = bid * THREADS + tid; i <= m; i += stride) {
            const int b = (i < m) ? __ldg(&idx[i]) : n_rows;  // idx[m] = n
            const int a = (i > 0) ? __ldg(&idx[i - 1]) : -1;
            for (int r = a + 1; r <= b; ++r) g_starts[r] = i;
        }
        __threadfence();
        __syncthreads();
        if (tid == 0) atomicAdd(&g_p1_done, 1);
        return;
    }

    // ---------- pass 2: champion scatter-add, one warp per row ----------
    const int warp = (bid - P1_BLOCKS) * (THREADS / 32) + (tid >> 5);
    const int lane = tid & 31;
    const int r = warp;
    const bool live = (r < n_rows);

    const float4* __restrict__ selfv = reinterpret_cast<const float4*>(self_t);
    const float4* __restrict__ valv  = reinterpret_cast<const float4*>(value);
    float4* __restrict__ outv        = reinterpret_cast<float4*>(out);

    // self row load is independent of pass-1: issue before the wait
    float4 acc = make_float4(0.f, 0.f, 0.f, 0.f);
    if (live) acc = __ldcs(&selfv[(size_t)r * D4 + lane]);

    // wait for pass-1 completion (one thread polls, block syncs)
    if (tid == 0) {
        while (atomicAdd(&g_p1_done, 0) < P1_BLOCKS) {}
        __threadfence();
    }
    __syncthreads();

    if (live) {
        int s = 0;
        if (lane < 2) s = g_starts[r + lane];
        const int start = __shfl_sync(0xffffffffu, s, 0);
        const int end   = __shfl_sync(0xffffffffu, s, 1);

        const float4* p = valv + (size_t)start * D4 + lane;
        int n = end - start;

        while (n >= 4) {
            float4 v0 = __ldcs(p);
            float4 v1 = __ldcs(p + D4);
            float4 v2 = __ldcs(p + 2 * D4);
            float4 v3 = __ldcs(p + 3 * D4);
            acc.x += v0.x; acc.y += v0.y; acc.z += v0.z; acc.w += v0.w;
            acc.x += v1.x; acc.y += v1.y; acc.z += v1.z; acc.w += v1.w;
            acc.x += v2.x; acc.y += v2.y; acc.z += v2.z; acc.w += v2.w;
            acc.x += v3.x; acc.y += v3.y; acc.z += v3.z; acc.w += v3.w;
            p += 4 * D4;
            n -= 4;
        }
        if (n >= 2) {
            float4 v0 = __ldcs(p);
            float4 v1 = __ldcs(p + D4);
            acc.x += v0.x; acc.y += v0.y; acc.z += v0.z; acc.w += v0.w;
            acc.x += v1.x; acc.y += v1.y; acc.z += v1.z; acc.w += v1.w;
            p += 2 * D4;
            n -= 2;
        }
        if (n) {
            float4 v = __ldcs(p);
            acc.x += v.x; acc.y += v.y; acc.z += v.z; acc.w += v.w;
        }

        __stcs(&outv[(size_t)r * D4 + lane], acc);
    }

    // ---------- epilogue: last pass-2 block resets counters ----------
    __syncthreads();
    if (tid == 0) {
        const int v = atomicAdd(&g_p2_done, 1);
        if (v == p2_blocks - 1) {
            atomicExch(&g_p1_done, 0);
            atomicExch(&g_p2_done, 0);
        }
    }
}

extern "C" void kernel_launch(void* const* d_in, const int* in_sizes, int n_in,
                              void* d_out, int out_size) {
    const float* self_t = (const float*)d_in[0];  // (N, 128) fp32
    const float* value  = (const float*)d_in[1];  // (M, 128) fp32
    const int*   idx    = (const int*)d_in[2];    // (M,) sorted
    // d_in[3] = pos, unused

    const int m      = in_sizes[2];       // 1048576
    const int n_rows = out_size / 128;    // 262144 (<= MAX_ROWS)

    const int warps_per_block = THREADS / 32;                 // 4
    const int p2_blocks = (n_rows + warps_per_block - 1) / warps_per_block;
    const int blocks = P1_BLOCKS + p2_blocks;

    fused_two_pass_kernel<<<blocks, THREADS>>>(self_t, value, idx,
                                               (float*)d_out,
                                               n_rows, m, p2_blocks);
}

// round 14
// speedup vs baseline: 1.1549x; 1.1549x over previous
#include <cuda_runtime.h>
#include <cstdint>

// out = self_tensor; out[sorted_index[i], :] += value[i, :]
// N=262144 rows, M=1048576 updates, D=128 cols, fp32. sorted_index SORTED,
// delivered as int32 by the harness.
//
// FINAL (converged champion, best total 121.34us):
// Pass 1: CSR row-start offsets (starts[r] = lower_bound(idx, r),
//   starts[N] = M). One load per element: thread i loads idx[i], obtains
//   idx[i-1] via __shfl_up; only lane 0 loads its warp boundary; the i==m
//   thread closes the tail.
// Pass 2: one warp per output row; 2 coalesced L2-hit loads of starts,
//   then streams the run of value rows (float4, 4-deep batched) on top of
//   the self row, single store. Zero atomics; exactly the minimal 776MB
//   traffic; measured ~6.93TB/s = 87% of HBM spec = this chip's streaming
//   ceiling. Evict-first hints keep idx/starts L2-resident.
//
// Rejected by measurement: fused single-kernel variants (value-centric
// CHUNK=32/8, software grid barrier), 2-rows-per-warp, PDL overlap, int4
// pass-1 — all neutral or regressions. Occupancy-maximal 1-row/warp shape
// is the optimum for this memory system.

static constexpr int D4 = 32;          // 128 floats = 32 float4/row
static constexpr int MAX_ROWS = 262144;

__device__ int g_starts[MAX_ROWS + 1];

__global__ void build_starts_kernel(const int* __restrict__ idx,
                                    int m, int n_rows) {
    const unsigned FULL = 0xffffffffu;
    const int i = blockIdx.x * blockDim.x + threadIdx.x;
    const int lane = threadIdx.x & 31;

    const int b = (i < m) ? __ldg(&idx[i]) : n_rows;   // virtual idx[m] = n
    int a = __shfl_up_sync(FULL, b, 1);
    if (lane == 0)                                     // warp-boundary element
        a = (i > 0) ? __ldg(&idx[i - 1]) : -1;

    if (i > m) return;
    if (i == m) a = (m > 0) ? __ldg(&idx[m - 1]) : -1; // tail closer
    for (int r = a + 1; r <= b; ++r) g_starts[r] = i;
}

__global__ void scatter_add_rows_kernel(const float* __restrict__ self_t,
                                        const float* __restrict__ value,
                                        float* __restrict__ out,
                                        int n_rows) {
    const int warp = (blockIdx.x * blockDim.x + threadIdx.x) >> 5;
    const int lane = threadIdx.x & 31;
    if (warp >= n_rows) return;

    const int r = warp;

    const float4* __restrict__ selfv = reinterpret_cast<const float4*>(self_t);
    const float4* __restrict__ valv  = reinterpret_cast<const float4*>(value);
    float4* __restrict__ outv        = reinterpret_cast<float4*>(out);

    // self row load issued early, overlaps the starts lookup
    float4 acc = __ldcs(&selfv[(size_t)r * D4 + lane]);

    int s = 0;
    if (lane < 2) s = g_starts[r + lane];
    const int start = __shfl_sync(0xffffffffu, s, 0);
    const int end   = __shfl_sync(0xffffffffu, s, 1);

    const float4* p = valv + (size_t)start * D4 + lane;
    int n = end - start;

    while (n >= 4) {
        float4 v0 = __ldcs(p);
        float4 v1 = __ldcs(p + D4);
        float4 v2 = __ldcs(p + 2 * D4);
        float4 v3 = __ldcs(p + 3 * D4);
        acc.x += v0.x; acc.y += v0.y; acc.z += v0.z; acc.w += v0.w;
        acc.x += v1.x; acc.y += v1.y; acc.z += v1.z; acc.w += v1.w;
        acc.x += v2.x; acc.y += v2.y; acc.z += v2.z; acc.w += v2.w;
        acc.x += v3.x; acc.y += v3.y; acc.z += v3.z; acc.w += v3.w;
        p += 4 * D4;
        n -= 4;
    }
    if (n >= 2) {
        float4 v0 = __ldcs(p);
        float4 v1 = __ldcs(p + D4);
        acc.x += v0.x; acc.y += v0.y; acc.z += v0.z; acc.w += v0.w;
        acc.x += v1.x; acc.y += v1.y; acc.z += v1.z; acc.w += v1.w;
        p += 2 * D4;
        n -= 2;
    }
    if (n) {
        float4 v = __ldcs(p);
        acc.x += v.x; acc.y += v.y; acc.z += v.z; acc.w += v.w;
    }

    __stcs(&outv[(size_t)r * D4 + lane], acc);
}

extern "C" void kernel_launch(void* const* d_in, const int* in_sizes, int n_in,
                              void* d_out, int out_size) {
    const float* self_t = (const float*)d_in[0];  // (N, 128) fp32
    const float* value  = (const float*)d_in[1];  // (M, 128) fp32
    const int*   idx    = (const int*)d_in[2];    // (M,) sorted
    // d_in[3] = pos, unused

    const int m      = in_sizes[2];       // 1048576
    const int n_rows = out_size / 128;    // 262144 (<= MAX_ROWS)

    {
        const int threads = 512;
        const int blocks = (m + 1 + threads - 1) / threads;
        build_starts_kernel<<<blocks, threads>>>(idx, m, n_rows);
    }
    {
        const int threads = 256;          // 8 warps/block, 1 row/warp
        const int blocks = (n_rows * 32 + threads - 1) / threads;
        scatter_add_rows_kernel<<<blocks, threads>>>(self_t, value,
                                                     (float*)d_out, n_rows);
    }
}